// round 10
// baseline (speedup 1.0000x reference)
#include <cuda_runtime.h>
#include <cstdint>

#define BATCH 8
#define NPTS  8192
#define NS    2048
#define KNBR  32
#define TB    512
#define NFC   4              // FPS CTAs (2 batches each)
#define PPT   32             // points per thread-of-half (8192 / 256)
#define NPAIR 16
#define NWARP 16             // consumer warps per block

typedef unsigned long long u64;

// scratch
__device__ float    g_new_xyz[BATCH * NS * 3];
__device__ unsigned g_progress[BATCH];

__device__ __forceinline__ unsigned ld_acq(const unsigned* p) {
    unsigned v;
    asm volatile("ld.acquire.gpu.global.u32 %0, [%1];" : "=r"(v) : "l"(p) : "memory");
    return v;
}
__device__ __forceinline__ void st_rel(unsigned* p, unsigned v) {
    asm volatile("st.release.gpu.global.u32 [%0], %1;" :: "l"(p), "r"(v) : "memory");
}

// packed f32x2 helpers (two independent IEEE f32 ops per instruction)
__device__ __forceinline__ u64 pk2(float lo, float hi) {
    u64 r;
    asm("mov.b64 %0, {%1, %2};" : "=l"(r) : "f"(lo), "f"(hi));
    return r;
}
__device__ __forceinline__ u64 add2(u64 a, u64 b) {
    u64 r;
    asm("add.rn.f32x2 %0, %1, %2;" : "=l"(r) : "l"(a), "l"(b));
    return r;
}
__device__ __forceinline__ u64 mul2(u64 a, u64 b) {
    u64 r;
    asm("mul.rn.f32x2 %0, %1, %2;" : "=l"(r) : "l"(a), "l"(b));
    return r;
}

extern "C" __global__ void reset_kernel() {
    if (threadIdx.x < BATCH) g_progress[threadIdx.x] = 0;
}

// ---------------------------------------------------------------------------
// Fused kernel. Blocks 0..3: FPS producers, TWO batches per CTA:
//   warps 0-7  -> batch 2*cta   (named barrier 1)
//   warps 8-15 -> batch 2*cta+1 (named barrier 2)
// Half 1 is phase-staggered by ~half an iteration so the two halves run in
// anti-phase: one half's serial reduction tail overlaps the other half's
// compute on the shared SMSPs (round-9 ran them in lockstep -> tails added).
// x lives in registers; y,z in smem pair layout (LDS.64 -> packed operand).
// Blocks 4..: warp-per-centroid ball query + MLP + max pool.
// ---------------------------------------------------------------------------
extern "C" __global__ void __launch_bounds__(TB, 1)
fused_kernel(const float* __restrict__ xyz,
             const float* __restrict__ w1, const float* __restrict__ b1,
             const float* __restrict__ w2, const float* __restrict__ b2,
             const float* __restrict__ w3, const float* __restrict__ b3,
             float* __restrict__ out)
{
    extern __shared__ float sm[];
    const int t    = threadIdx.x;
    const int lane = t & 31;

    if (blockIdx.x < NFC) {
        // ================= FPS producer (2 independent halves) =============
        u64* xp   = (u64*)sm;            // 2 halves * 4096 entries (64 KB)
        u64* yp   = xp + 8192;           // 64 KB
        u64* zp   = yp + 8192;           // 64 KB
        u64* skey = zp + 8192;           // [h][par][w8] = 2*2*8 entries
        float* xpF = (float*)xp;
        float* ypF = (float*)yp;
        float* zpF = (float*)zp;

        const int t_h = t & 255;         // thread id within half
        const int h   = t >> 8;          // half = which batch of this CTA
        const int bb  = (blockIdx.x << 1) | h;
        const float* base = xyz + (size_t)bb * NPTS * 3;

        // init: load coords into pair layout
        for (int k = 0; k < PPT; k++) {
            int i   = t_h + k * 256;
            int off = h * 8192 + (((k >> 1) * 256 + t_h) << 1) + (k & 1);
            xpF[off] = base[i * 3 + 0];
            ypF[off] = base[i * 3 + 1];
            zpF[off] = base[i * 3 + 2];
        }
        __syncthreads();

        u64 px2[NPAIR];                  // only x in registers
        int ddI[PPT];
#pragma unroll
        for (int p = 0; p < NPAIR; p++)
            px2[p] = xp[h * 4096 + p * 256 + t_h];
#pragma unroll
        for (int i = 0; i < PPT; i++) ddI[i] = __float_as_int(1e10f);

        // phase stagger: push half 1 ~half an iteration behind half 0 so the
        // halves settle into anti-phase (tail of one overlaps compute of the
        // other). Offset persists: a half stalled at its named barrier frees
        // all issue slots to the other half.
        if (h == 1) __nanosleep(340);

        int far = 0;
        float* out_xyz = out + (size_t)bb * 3 * NS;
        float* gx      = g_new_xyz + (size_t)bb * NS * 3;

        for (int s = 0; s < NS; s++) {
            const int par = s & 1;
            // centroid lookup (scalar, broadcast LDS)
            int k    = far >> 8;
            int tidf = far & 255;
            int coff = h * 8192 + (((k >> 1) * 256 + tidf) << 1) + (k & 1);
            float cx = xpF[coff], cy = ypF[coff], cz = zpF[coff];
            if (t_h == 0) {
                out_xyz[0 * NS + s] = cx;
                out_xyz[1 * NS + s] = cy;
                out_xyz[2 * NS + s] = cz;
                gx[s * 3 + 0] = cx; gx[s * 3 + 1] = cy; gx[s * 3 + 2] = cz;
                if ((s & 15) == 15) st_rel(&g_progress[bb], (unsigned)(s + 1));
            }
            // negation exact: a + (-c) == a - c
            u64 ncx = pk2(-cx, -cx);
            u64 ncy = pk2(-cy, -cy);
            u64 ncz = pk2(-cz, -cz);

            int bvI  = (int)0x80000000;
            int slot = 0;
#pragma unroll
            for (int p = 0; p < NPAIR; p++) {
                u64 ypair = yp[h * 4096 + p * 256 + t_h];   // LDS.64 packed
                u64 zpair = zp[h * 4096 + p * 256 + t_h];   // LDS.64 packed
                u64 dx = add2(px2[p], ncx);
                u64 dy = add2(ypair, ncy);
                u64 dz = add2(zpair, ncz);
                dx = mul2(dx, dx);
                dy = mul2(dy, dy);
                dz = mul2(dz, dz);
                u64 d2 = add2(add2(dx, dy), dz);            // (x2+y2)+z2
                // integer min/compare on nonneg float bits == float semantics
                int dlo = (int)(unsigned)d2;
                int dhi = (int)(d2 >> 32);
                int o0  = ddI[2 * p + 0];
                int o1  = ddI[2 * p + 1];
                int n0  = (dlo < o0) ? dlo : o0; ddI[2 * p + 0] = n0;
                int n1  = (dhi < o1) ? dhi : o1; ddI[2 * p + 1] = n1;
                // ascending slot = ascending original idx: strict > keeps
                // the lowest index on ties (matches jnp.argmax)
                if (n0 > bvI) { bvI = n0; slot = 2 * p + 0; }
                if (n1 > bvI) { bvI = n1; slot = 2 * p + 1; }
            }
            // stage 1: warp argmax via REDUX (lowest index on ties)
            int mb = __reduce_max_sync(0xffffffffu, bvI);
            int bi = t_h + slot * 256;
            int ca = (bvI == mb) ? bi : 0x7fffffff;
            int wi = __reduce_min_sync(0xffffffffu, ca);
            if (lane == 0) {
                skey[h * 16 + par * 8 + (t_h >> 5)] =
                    ((u64)(unsigned)mb << 32) | (unsigned)(~wi);
            }
            // half-private barrier (ids 1,2; 256 threads each)
            asm volatile("bar.sync %0, %1;" :: "r"(1 + h), "r"(256) : "memory");
            // stage 2: every warp combines the 8 warp winners
            u64 kk = skey[h * 16 + par * 8 + (lane & 7)];
            int      hv = (int)(kk >> 32);
            unsigned lv = (unsigned)kk;
            int m2 = __reduce_max_sync(0xffffffffu, hv);
            unsigned cand = (hv == m2) ? lv : 0u;
            unsigned mi = __reduce_max_sync(0xffffffffu, cand);
            far = (int)(~mi);
        }
        if (t_h == 0) st_rel(&g_progress[bb], (unsigned)NS);
    } else {
        // ================= MLP consumer =================
        float* w1s = sm;              // 64x3
        float* b1s = w1s + 192;       // 64
        float* w2t = b1s + 64;        // 64x64 transposed [c][o]
        float* b2s = w2t + 4096;      // 64
        float* w3s = b2s + 64;        // 128x64 row-major [o][c]
        float* b3s = w3s + 8192;      // 128
        int*   lists = (int*)(b3s + 128);  // NWARP * 32

        const int w = t >> 5;

        for (int i = t; i < 192; i += TB) w1s[i] = w1[i];
        if (t < 64) { b1s[t] = b1[t]; b2s[t] = b2[t]; }
        for (int i = t; i < 4096; i += TB) {
            int o = i >> 6, c = i & 63;
            w2t[c * 64 + o] = w2[i];
        }
        for (int i = t; i < 8192; i += TB) w3s[i] = w3[i];
        if (t < 128) b3s[t] = b3[t];

        // block mapping: batch b, s range [sbase, sbase+16)
        const int idx   = blockIdx.x - NFC;        // 0..1023
        const int b     = idx & 7;
        const int sbase = (idx >> 3) * NWARP;
        const int s     = sbase + w;

        // single poller per block, coarse gate on the whole block's range
        if (t == 0) {
            unsigned need = (unsigned)(sbase + NWARP);
            while (ld_acq(&g_progress[b]) < need) __nanosleep(2048);
        }
        __syncthreads();

        const float* xb   = xyz + (size_t)b * NPTS * 3;
        const float* cptr = g_new_xyz + ((size_t)b * NS + s) * 3;
        const float cx = cptr[0], cy = cptr[1], cz = cptr[2];

        // --- ball query: first KNBR points (ascending idx) with d2 <= r^2 ---
        int* list = lists + w * KNBR;
        int  cnt  = 0;
        for (int basei = 0; basei < NPTS; basei += 32) {
            int pi = basei + lane;
            float x = xb[pi * 3 + 0];
            float y = xb[pi * 3 + 1];
            float z = xb[pi * 3 + 2];
            float dx = __fsub_rn(x, cx);
            float dy = __fsub_rn(y, cy);
            float dz = __fsub_rn(z, cz);
            float d  = __fadd_rn(__fadd_rn(__fmul_rn(dx, dx), __fmul_rn(dy, dy)),
                                 __fmul_rn(dz, dz));
            bool within = (d <= 0.04f);
            unsigned m  = __ballot_sync(0xffffffffu, within);
            if (within) {
                int pos = cnt + __popc(m & ((1u << lane) - 1u));
                if (pos < KNBR) list[pos] = pi;
            }
            cnt += __popc(m);
            if (cnt >= KNBR) break;
        }
        __syncwarp();
        const int nb = list[(lane < cnt) ? lane : 0];

        const float rx = xb[nb * 3 + 0] - cx;
        const float ry = xb[nb * 3 + 1] - cy;
        const float rz = xb[nb * 3 + 2] - cz;

        // --- layer1 fused into layer2 accumulation ---
        float h2[64];
#pragma unroll
        for (int o = 0; o < 64; o++) h2[o] = b2s[o];

        for (int c = 0; c < 64; c++) {
            float a = fmaf(rx, w1s[c * 3 + 0], b1s[c]);
            a = fmaf(ry, w1s[c * 3 + 1], a);
            a = fmaf(rz, w1s[c * 3 + 2], a);
            float hv = fmaxf(a, 0.0f);
            const float4* row = (const float4*)(w2t + c * 64);
#pragma unroll
            for (int o4 = 0; o4 < 16; o4++) {
                float4 wv = row[o4];
                h2[o4 * 4 + 0] = fmaf(hv, wv.x, h2[o4 * 4 + 0]);
                h2[o4 * 4 + 1] = fmaf(hv, wv.y, h2[o4 * 4 + 1]);
                h2[o4 * 4 + 2] = fmaf(hv, wv.z, h2[o4 * 4 + 2]);
                h2[o4 * 4 + 3] = fmaf(hv, wv.w, h2[o4 * 4 + 3]);
            }
        }
#pragma unroll
        for (int o = 0; o < 64; o++) h2[o] = fmaxf(h2[o], 0.0f);

        // --- layer3 + relu + warp max-pool ---
        float* outb = out + (size_t)BATCH * 3 * NS + (size_t)b * 128 * NS + s;
        for (int o = 0; o < 128; o++) {
            float a = b3s[o];
            const float4* row = (const float4*)(w3s + o * 64);
#pragma unroll
            for (int c4 = 0; c4 < 16; c4++) {
                float4 wv = row[c4];
                a = fmaf(h2[c4 * 4 + 0], wv.x, a);
                a = fmaf(h2[c4 * 4 + 1], wv.y, a);
                a = fmaf(h2[c4 * 4 + 2], wv.z, a);
                a = fmaf(h2[c4 * 4 + 3], wv.w, a);
            }
            a = fmaxf(a, 0.0f);
#pragma unroll
            for (int off = 16; off; off >>= 1)
                a = fmaxf(a, __shfl_xor_sync(0xffffffffu, a, off));
            if (lane == 0) outb[(size_t)o * NS] = a;
        }
    }
}

// ---------------------------------------------------------------------------
extern "C" void kernel_launch(void* const* d_in, const int* in_sizes, int n_in,
                              void* d_out, int out_size)
{
    const float* xyz = (const float*)d_in[0];
    const float* w1 = (const float*)d_in[2];
    const float* b1 = (const float*)d_in[3];
    const float* w2 = (const float*)d_in[4];
    const float* b2 = (const float*)d_in[5];
    const float* w3 = (const float*)d_in[6];
    const float* b3 = (const float*)d_in[7];

    float* out = (float*)d_out;

    // FPS: xp+yp+zp pair arrays (3 * 64KB) + skey
    const int smem = 3 * 8192 * (int)sizeof(u64) + 512;   // ~192.5 KB
    cudaFuncSetAttribute(fused_kernel,
                         cudaFuncAttributeMaxDynamicSharedMemorySize, smem);

    const int nmlp = (BATCH * NS) / NWARP;       // 1024 consumer blocks
    reset_kernel<<<1, 32>>>();
    fused_kernel<<<NFC + nmlp, TB, smem>>>(xyz, w1, b1, w2, b2, w3, b3, out);
}

// round 12
// speedup vs baseline: 1.8194x; 1.8194x over previous
#include <cuda_runtime.h>
#include <cstdint>

#define BATCH 8
#define NPTS  8192
#define NS    2048
#define KNBR  32
#define TB    512
#define PPT   16             // points per thread in FPS
#define NPAIR (PPT / 2)      // 8 packed pairs
#define NWARP (TB / 32)      // 16

typedef unsigned long long u64;

// scratch
__device__ float    g_new_xyz[BATCH * NS * 3];
__device__ unsigned g_progress[BATCH];

__device__ __forceinline__ unsigned ld_acq(const unsigned* p) {
    unsigned v;
    asm volatile("ld.acquire.gpu.global.u32 %0, [%1];" : "=r"(v) : "l"(p) : "memory");
    return v;
}
__device__ __forceinline__ void st_rel(unsigned* p, unsigned v) {
    asm volatile("st.release.gpu.global.u32 [%0], %1;" :: "l"(p), "r"(v) : "memory");
}

// packed f32x2 helpers (two independent IEEE f32 ops per instruction)
__device__ __forceinline__ u64 pk2(float lo, float hi) {
    u64 r;
    asm("mov.b64 %0, {%1, %2};" : "=l"(r) : "f"(lo), "f"(hi));
    return r;
}
__device__ __forceinline__ u64 add2(u64 a, u64 b) {
    u64 r;
    asm("add.rn.f32x2 %0, %1, %2;" : "=l"(r) : "l"(a), "l"(b));
    return r;
}
__device__ __forceinline__ u64 mul2(u64 a, u64 b) {
    u64 r;
    asm("mul.rn.f32x2 %0, %1, %2;" : "=l"(r) : "l"(a), "l"(b));
    return r;
}

extern "C" __global__ void reset_kernel() {
    if (threadIdx.x < BATCH) g_progress[threadIdx.x] = 0;
}

// ---------------------------------------------------------------------------
// Fused kernel. Blocks 0..7: FPS producer (one per batch).
// Blocks 8..: 16 warps, each handling one centroid: ball query + MLP + pool.
// ---------------------------------------------------------------------------
extern "C" __global__ void __launch_bounds__(TB, 1)
fused_kernel(const float* __restrict__ xyz,
             const float* __restrict__ w1, const float* __restrict__ b1,
             const float* __restrict__ w2, const float* __restrict__ b2,
             const float* __restrict__ w3, const float* __restrict__ b3,
             float* __restrict__ out)
{
    extern __shared__ float sm[];
    const int t    = threadIdx.x;
    const int lane = t & 31;
    const int w    = t >> 5;

    if (blockIdx.x < BATCH) {
        // ================= FPS producer =================
        __shared__ u64 skey2[2][32];    // [parity][warp or zero-pad]
        float* sx = sm;
        float* sy = sm + NPTS;
        float* sz = sm + 2 * NPTS;

        const int b = blockIdx.x;
        const float* base = xyz + (size_t)b * NPTS * 3;

        if (t < 64) {                   // zero the pad slots (lanes 16..31)
            int pp = t >> 5, ll = t & 31;
            if (ll >= NWARP) skey2[pp][ll] = 0ull;
        }

        for (int i = t; i < NPTS; i += TB) {
            sx[i] = base[i * 3 + 0];
            sy[i] = base[i * 3 + 1];
            sz[i] = base[i * 3 + 2];
        }
        __syncthreads();

        // pair p holds points idx = t + (2p)*TB (lo) and t + (2p+1)*TB (hi)
        // dd kept as int bit-patterns (all values >= 0 -> int order == float
        // order), so min/max/compare run on the ALU pipe (IMNMX/ISETP).
        u64 px2[NPAIR], py2[NPAIR], pz2[NPAIR];
        int ddlo[NPAIR], ddhi[NPAIR];
#pragma unroll
        for (int p = 0; p < NPAIR; p++) {
            int i0 = t + (2 * p) * TB;
            int i1 = t + (2 * p + 1) * TB;
            px2[p] = pk2(sx[i0], sx[i1]);
            py2[p] = pk2(sy[i0], sy[i1]);
            pz2[p] = pk2(sz[i0], sz[i1]);
            ddlo[p] = __float_as_int(1e10f);
            ddhi[p] = __float_as_int(1e10f);
        }

        int far = 0;
        float* out_xyz = out + (size_t)b * 3 * NS;
        float* gx      = g_new_xyz + (size_t)b * NS * 3;

        for (int s = 0; s < NS; s++) {
            const int par = s & 1;
            float cx = sx[far], cy = sy[far], cz = sz[far];
            if (t == 0) {
                out_xyz[0 * NS + s] = cx;
                out_xyz[1 * NS + s] = cy;
                out_xyz[2 * NS + s] = cz;
                gx[s * 3 + 0] = cx; gx[s * 3 + 1] = cy; gx[s * 3 + 2] = cz;
                if ((s & 15) == 15) st_rel(&g_progress[b], (unsigned)(s + 1));
            }
            // negation exact: a + (-c) == a - c
            u64 ncx = pk2(-cx, -cx);
            u64 ncy = pk2(-cy, -cy);
            u64 ncz = pk2(-cz, -cz);

#pragma unroll
            for (int p = 0; p < NPAIR; p++) {
                u64 dx = add2(px2[p], ncx);
                u64 dy = add2(py2[p], ncy);
                u64 dz = add2(pz2[p], ncz);
                dx = mul2(dx, dx);
                dy = mul2(dy, dy);
                dz = mul2(dz, dz);
                u64 d2 = add2(add2(dx, dy), dz);   // (x2+y2)+z2, exact order
                int dlo = (int)(unsigned)d2;
                int dhi = (int)(d2 >> 32);
                ddlo[p] = (dlo < ddlo[p]) ? dlo : ddlo[p];   // IMNMX
                ddhi[p] = (dhi < ddhi[p]) ? dhi : ddhi[p];   // IMNMX
            }
            // per-thread max via int tree (15 IMNMX)
            int m0 = (ddlo[0] > ddhi[0]) ? ddlo[0] : ddhi[0];
            int m1 = (ddlo[1] > ddhi[1]) ? ddlo[1] : ddhi[1];
            int m2_ = (ddlo[2] > ddhi[2]) ? ddlo[2] : ddhi[2];
            int m3 = (ddlo[3] > ddhi[3]) ? ddlo[3] : ddhi[3];
            int m4 = (ddlo[4] > ddhi[4]) ? ddlo[4] : ddhi[4];
            int m5 = (ddlo[5] > ddhi[5]) ? ddlo[5] : ddhi[5];
            int m6 = (ddlo[6] > ddhi[6]) ? ddlo[6] : ddhi[6];
            int m7 = (ddlo[7] > ddhi[7]) ? ddlo[7] : ddhi[7];
            m0 = (m0 > m1) ? m0 : m1;
            m2_ = (m2_ > m3) ? m2_ : m3;
            m4 = (m4 > m5) ? m4 : m5;
            m6 = (m6 > m7) ? m6 : m7;
            m0 = (m0 > m2_) ? m0 : m2_;
            m4 = (m4 > m6) ? m4 : m6;
            int v = (m0 > m4) ? m0 : m4;
            int mb = __reduce_max_sync(0xffffffffu, v);
            // lowest slot with dd == mb (bit-equal); threads without a match
            // get slot 99 -> idx > any real idx, dropped by REDUX-min.
            // Descending loop: final write = lowest slot = lowest orig index.
            int slot = 99;
#pragma unroll
            for (int p = NPAIR - 1; p >= 0; p--) {
                if (ddhi[p] == mb) slot = 2 * p + 1;
                if (ddlo[p] == mb) slot = 2 * p;
            }
            int myidx = t + slot * TB;   // idx order == (slot, t) lex order
            int wi = __reduce_min_sync(0xffffffffu, myidx);
            if (lane == 0) {
                skey2[par][w] = ((u64)(unsigned)mb << 32) | (unsigned)(~wi);
            }
            __syncthreads();
            // combine all 16 warp winners (+16 zero pads) in every warp
            u64 kk = skey2[par][lane];
            int      hv = (int)(kk >> 32);
            unsigned lv = (unsigned)kk;
            int mB = __reduce_max_sync(0xffffffffu, hv);
            unsigned cand = (hv == mB) ? lv : 0u;
            unsigned mi = __reduce_max_sync(0xffffffffu, cand);
            far = (int)(~mi);
        }
        if (t == 0) st_rel(&g_progress[b], (unsigned)NS);
    } else {
        // ================= MLP consumer =================
        float* w1s = sm;              // 64x3
        float* b1s = w1s + 192;       // 64
        float* w2t = b1s + 64;        // 64x64 transposed [c][o]
        float* b2s = w2t + 4096;      // 64
        float* w3s = b2s + 64;        // 128x64 row-major [o][c]
        float* b3s = w3s + 8192;      // 128
        int*   lists = (int*)(b3s + 128);  // NWARP * 32

        for (int i = t; i < 192; i += TB) w1s[i] = w1[i];
        if (t < 64) { b1s[t] = b1[t]; b2s[t] = b2[t]; }
        for (int i = t; i < 4096; i += TB) {
            int o = i >> 6, c = i & 63;
            w2t[c * 64 + o] = w2[i];
        }
        for (int i = t; i < 8192; i += TB) w3s[i] = w3[i];
        if (t < 128) b3s[t] = b3[t];

        // block mapping: batch b, s range [sbase, sbase+16)
        const int idx   = blockIdx.x - BATCH;      // 0..1023
        const int b     = idx & 7;
        const int sbase = (idx >> 3) * NWARP;
        const int s     = sbase + w;

        // single poller per block, coarse gate on the whole block's range
        if (t == 0) {
            unsigned need = (unsigned)(sbase + NWARP);
            while (ld_acq(&g_progress[b]) < need) __nanosleep(2048);
        }
        __syncthreads();

        const float* xb   = xyz + (size_t)b * NPTS * 3;
        const float* cptr = g_new_xyz + ((size_t)b * NS + s) * 3;
        const float cx = cptr[0], cy = cptr[1], cz = cptr[2];

        // --- ball query: first KNBR points (ascending idx) with d2 <= r^2 ---
        int* list = lists + w * KNBR;
        int  cnt  = 0;
        for (int basei = 0; basei < NPTS; basei += 32) {
            int pi = basei + lane;
            float x = xb[pi * 3 + 0];
            float y = xb[pi * 3 + 1];
            float z = xb[pi * 3 + 2];
            float dx = __fsub_rn(x, cx);
            float dy = __fsub_rn(y, cy);
            float dz = __fsub_rn(z, cz);
            float d  = __fadd_rn(__fadd_rn(__fmul_rn(dx, dx), __fmul_rn(dy, dy)),
                                 __fmul_rn(dz, dz));
            bool within = (d <= 0.04f);
            unsigned m  = __ballot_sync(0xffffffffu, within);
            if (within) {
                int pos = cnt + __popc(m & ((1u << lane) - 1u));
                if (pos < KNBR) list[pos] = pi;
            }
            cnt += __popc(m);
            if (cnt >= KNBR) break;
        }
        __syncwarp();
        const int nb = list[(lane < cnt) ? lane : 0];

        const float rx = xb[nb * 3 + 0] - cx;
        const float ry = xb[nb * 3 + 1] - cy;
        const float rz = xb[nb * 3 + 2] - cz;

        // --- layer1 fused into layer2 accumulation ---
        float h2[64];
#pragma unroll
        for (int o = 0; o < 64; o++) h2[o] = b2s[o];

        for (int c = 0; c < 64; c++) {
            float a = fmaf(rx, w1s[c * 3 + 0], b1s[c]);
            a = fmaf(ry, w1s[c * 3 + 1], a);
            a = fmaf(rz, w1s[c * 3 + 2], a);
            float hv = fmaxf(a, 0.0f);
            const float4* row = (const float4*)(w2t + c * 64);
#pragma unroll
            for (int o4 = 0; o4 < 16; o4++) {
                float4 wv = row[o4];
                h2[o4 * 4 + 0] = fmaf(hv, wv.x, h2[o4 * 4 + 0]);
                h2[o4 * 4 + 1] = fmaf(hv, wv.y, h2[o4 * 4 + 1]);
                h2[o4 * 4 + 2] = fmaf(hv, wv.z, h2[o4 * 4 + 2]);
                h2[o4 * 4 + 3] = fmaf(hv, wv.w, h2[o4 * 4 + 3]);
            }
        }
#pragma unroll
        for (int o = 0; o < 64; o++) h2[o] = fmaxf(h2[o], 0.0f);

        // --- layer3 + relu + warp max-pool ---
        float* outb = out + (size_t)BATCH * 3 * NS + (size_t)b * 128 * NS + s;
        for (int o = 0; o < 128; o++) {
            float a = b3s[o];
            const float4* row = (const float4*)(w3s + o * 64);
#pragma unroll
            for (int c4 = 0; c4 < 16; c4++) {
                float4 wv = row[c4];
                a = fmaf(h2[c4 * 4 + 0], wv.x, a);
                a = fmaf(h2[c4 * 4 + 1], wv.y, a);
                a = fmaf(h2[c4 * 4 + 2], wv.z, a);
                a = fmaf(h2[c4 * 4 + 3], wv.w, a);
            }
            a = fmaxf(a, 0.0f);
#pragma unroll
            for (int off = 16; off; off >>= 1)
                a = fmaxf(a, __shfl_xor_sync(0xffffffffu, a, off));
            if (lane == 0) outb[(size_t)o * NS] = a;
        }
    }
}

// ---------------------------------------------------------------------------
extern "C" void kernel_launch(void* const* d_in, const int* in_sizes, int n_in,
                              void* d_out, int out_size)
{
    const float* xyz = (const float*)d_in[0];
    const float* w1 = (const float*)d_in[2];
    const float* b1 = (const float*)d_in[3];
    const float* w2 = (const float*)d_in[4];
    const float* b2 = (const float*)d_in[5];
    const float* w3 = (const float*)d_in[6];
    const float* b3 = (const float*)d_in[7];

    float* out = (float*)d_out;

    const int smem = 3 * NPTS * sizeof(float);   // 96 KB
    cudaFuncSetAttribute(fused_kernel,
                         cudaFuncAttributeMaxDynamicSharedMemorySize, smem);

    const int nmlp = (BATCH * NS) / NWARP;       // 1024 consumer blocks
    reset_kernel<<<1, 32>>>();
    fused_kernel<<<BATCH + nmlp, TB, smem>>>(xyz, w1, b1, w2, b2, w3, b3, out);
}

// round 13
// speedup vs baseline: 1.9456x; 1.0693x over previous
#include <cuda_runtime.h>
#include <cstdint>

#define BATCH 8
#define NPTS  8192
#define NS    2048
#define KNBR  32
#define TB    512
#define PPT   16             // points per thread in FPS
#define NPAIR (PPT / 2)      // 8 packed pairs
#define NWARP (TB / 32)      // 16

typedef unsigned long long u64;

// scratch: centroids padded to float4 for single STG.128 publish
__device__ float    g_new_xyz[BATCH * NS * 4];
__device__ unsigned g_progress[BATCH];

__device__ __forceinline__ unsigned ld_acq(const unsigned* p) {
    unsigned v;
    asm volatile("ld.acquire.gpu.global.u32 %0, [%1];" : "=r"(v) : "l"(p) : "memory");
    return v;
}
__device__ __forceinline__ void st_rel(unsigned* p, unsigned v) {
    asm volatile("st.release.gpu.global.u32 [%0], %1;" :: "l"(p), "r"(v) : "memory");
}

// packed f32x2 helpers (two independent IEEE f32 ops per instruction)
__device__ __forceinline__ u64 pk2(float lo, float hi) {
    u64 r;
    asm("mov.b64 %0, {%1, %2};" : "=l"(r) : "f"(lo), "f"(hi));
    return r;
}
__device__ __forceinline__ u64 add2(u64 a, u64 b) {
    u64 r;
    asm("add.rn.f32x2 %0, %1, %2;" : "=l"(r) : "l"(a), "l"(b));
    return r;
}
__device__ __forceinline__ u64 mul2(u64 a, u64 b) {
    u64 r;
    asm("mul.rn.f32x2 %0, %1, %2;" : "=l"(r) : "l"(a), "l"(b));
    return r;
}

extern "C" __global__ void reset_kernel() {
    if (threadIdx.x < BATCH) g_progress[threadIdx.x] = 0;
}

// ---------------------------------------------------------------------------
// Fused kernel. Blocks 0..7: FPS producer (one per batch).
// Blocks 8..: 16 warps, each handling one centroid: ball query + MLP + pool.
// ---------------------------------------------------------------------------
extern "C" __global__ void __launch_bounds__(TB, 1)
fused_kernel(const float* __restrict__ xyz,
             const float* __restrict__ w1, const float* __restrict__ b1,
             const float* __restrict__ w2, const float* __restrict__ b2,
             const float* __restrict__ w3, const float* __restrict__ b3,
             float* __restrict__ out)
{
    extern __shared__ float sm[];
    const int t    = threadIdx.x;
    const int lane = t & 31;
    const int w    = t >> 5;

    if (blockIdx.x < BATCH) {
        // ================= FPS producer =================
        __shared__ u64 skey2[2][32];    // [parity][warp or zero-pad]
        float* sx = sm;
        float* sy = sm + NPTS;
        float* sz = sm + 2 * NPTS;

        const int b = blockIdx.x;
        const float* base = xyz + (size_t)b * NPTS * 3;

        if (t < 64) {                   // zero the pad slots (lanes 16..31)
            int pp = t >> 5, ll = t & 31;
            if (ll >= NWARP) skey2[pp][ll] = 0ull;
        }

        for (int i = t; i < NPTS; i += TB) {
            sx[i] = base[i * 3 + 0];
            sy[i] = base[i * 3 + 1];
            sz[i] = base[i * 3 + 2];
        }
        __syncthreads();

        // pair p holds points idx = t + (2p)*TB (lo) and t + (2p+1)*TB (hi)
        // dd kept as int bit-patterns (all >= 0 -> int order == float order):
        // min/max/compare run on the ALU pipe (IMNMX/ISETP).
        u64 px2[NPAIR], py2[NPAIR], pz2[NPAIR];
        int ddlo[NPAIR], ddhi[NPAIR];
#pragma unroll
        for (int p = 0; p < NPAIR; p++) {
            int i0 = t + (2 * p) * TB;
            int i1 = t + (2 * p + 1) * TB;
            px2[p] = pk2(sx[i0], sx[i1]);
            py2[p] = pk2(sy[i0], sy[i1]);
            pz2[p] = pk2(sz[i0], sz[i1]);
            ddlo[p] = __float_as_int(1e10f);
            ddhi[p] = __float_as_int(1e10f);
        }

        int far = 0;
        float* out_xyz = out + (size_t)b * 3 * NS;
        float* gx4     = g_new_xyz + ((size_t)b * NS << 2);

        for (int s = 0; s < NS; s++) {
            const int par = s & 1;
            float cx = sx[far], cy = sy[far], cz = sz[far];
            // vectorized writer: one 3-lane STG for out planes (warp 0),
            // one STG.128 for the consumer-facing centroid (lane 0).
            if (w == 0) {
                if (lane < 3) {
                    float val = (lane == 0) ? cx : (lane == 1) ? cy : cz;
                    out_xyz[lane * NS + s] = val;
                }
                if (lane == 0) {
                    float4 c4 = make_float4(cx, cy, cz, 0.0f);
                    *(float4*)(gx4 + ((size_t)s << 2)) = c4;
                    if ((s & 15) == 15)
                        st_rel(&g_progress[b], (unsigned)(s + 1));
                }
            }
            // negation exact: a + (-c) == a - c
            u64 ncx = pk2(-cx, -cx);
            u64 ncy = pk2(-cy, -cy);
            u64 ncz = pk2(-cz, -cz);

#pragma unroll
            for (int p = 0; p < NPAIR; p++) {
                u64 dx = add2(px2[p], ncx);
                u64 dy = add2(py2[p], ncy);
                u64 dz = add2(pz2[p], ncz);
                dx = mul2(dx, dx);
                dy = mul2(dy, dy);
                dz = mul2(dz, dz);
                u64 d2 = add2(add2(dx, dy), dz);   // (x2+y2)+z2, exact order
                int dlo = (int)(unsigned)d2;
                int dhi = (int)(d2 >> 32);
                ddlo[p] = (dlo < ddlo[p]) ? dlo : ddlo[p];   // IMNMX
                ddhi[p] = (dhi < ddhi[p]) ? dhi : ddhi[p];   // IMNMX
            }
            // per-thread (max value, lowest slot holding it) via index tree.
            // Ties keep the lower slot => lowest global idx (idx = slot*TB+t).
            int v0[NPAIR], i0[NPAIR];
#pragma unroll
            for (int p = 0; p < NPAIR; p++) {
                // hi wins only strictly (lo has the lower slot)
                v0[p] = (ddhi[p] > ddlo[p]) ? ddhi[p] : ddlo[p];
                i0[p] = (ddhi[p] > ddlo[p]) ? (2 * p + 1) : (2 * p);
            }
#pragma unroll
            for (int stride = 1; stride < NPAIR; stride <<= 1) {
#pragma unroll
                for (int p = 0; p < NPAIR; p += 2 * stride) {
                    // right side wins only strictly (left has lower slots)
                    bool gt = (v0[p + stride] > v0[p]);
                    v0[p] = gt ? v0[p + stride] : v0[p];
                    i0[p] = gt ? i0[p + stride] : i0[p];
                }
            }
            int v  = v0[0];
            int mb = __reduce_max_sync(0xffffffffu, v);
            int myidx = (v == mb) ? (t + i0[0] * TB) : 0x7fffffff;
            int wi = __reduce_min_sync(0xffffffffu, myidx);
            if (lane == 0) {
                skey2[par][w] = ((u64)(unsigned)mb << 32) | (unsigned)(~wi);
            }
            __syncthreads();
            // combine all 16 warp winners (+16 zero pads) in every warp
            u64 kk = skey2[par][lane];
            int      hv = (int)(kk >> 32);
            unsigned lv = (unsigned)kk;
            int mB = __reduce_max_sync(0xffffffffu, hv);
            unsigned cand = (hv == mB) ? lv : 0u;
            unsigned mi = __reduce_max_sync(0xffffffffu, cand);
            far = (int)(~mi);
        }
        if (t == 0) st_rel(&g_progress[b], (unsigned)NS);
    } else {
        // ================= MLP consumer =================
        float* w1s = sm;              // 64x3
        float* b1s = w1s + 192;       // 64
        float* w2t = b1s + 64;        // 64x64 transposed [c][o]
        float* b2s = w2t + 4096;      // 64
        float* w3s = b2s + 64;        // 128x64 row-major [o][c]
        float* b3s = w3s + 8192;      // 128
        int*   lists = (int*)(b3s + 128);  // NWARP * 32

        for (int i = t; i < 192; i += TB) w1s[i] = w1[i];
        if (t < 64) { b1s[t] = b1[t]; b2s[t] = b2[t]; }
        for (int i = t; i < 4096; i += TB) {
            int o = i >> 6, c = i & 63;
            w2t[c * 64 + o] = w2[i];
        }
        for (int i = t; i < 8192; i += TB) w3s[i] = w3[i];
        if (t < 128) b3s[t] = b3[t];

        // block mapping: batch b, s range [sbase, sbase+16)
        const int idx   = blockIdx.x - BATCH;      // 0..1023
        const int b     = idx & 7;
        const int sbase = (idx >> 3) * NWARP;
        const int s     = sbase + w;

        // single poller per block, coarse gate on the whole block's range
        if (t == 0) {
            unsigned need = (unsigned)(sbase + NWARP);
            while (ld_acq(&g_progress[b]) < need) __nanosleep(2048);
        }
        __syncthreads();

        const float* xb   = xyz + (size_t)b * NPTS * 3;
        const float* cptr = g_new_xyz + (((size_t)b * NS + s) << 2);
        const float cx = cptr[0], cy = cptr[1], cz = cptr[2];

        // --- ball query: first KNBR points (ascending idx) with d2 <= r^2 ---
        int* list = lists + w * KNBR;
        int  cnt  = 0;
        for (int basei = 0; basei < NPTS; basei += 32) {
            int pi = basei + lane;
            float x = xb[pi * 3 + 0];
            float y = xb[pi * 3 + 1];
            float z = xb[pi * 3 + 2];
            float dx = __fsub_rn(x, cx);
            float dy = __fsub_rn(y, cy);
            float dz = __fsub_rn(z, cz);
            float d  = __fadd_rn(__fadd_rn(__fmul_rn(dx, dx), __fmul_rn(dy, dy)),
                                 __fmul_rn(dz, dz));
            bool within = (d <= 0.04f);
            unsigned m  = __ballot_sync(0xffffffffu, within);
            if (within) {
                int pos = cnt + __popc(m & ((1u << lane) - 1u));
                if (pos < KNBR) list[pos] = pi;
            }
            cnt += __popc(m);
            if (cnt >= KNBR) break;
        }
        __syncwarp();
        const int nb = list[(lane < cnt) ? lane : 0];

        const float rx = xb[nb * 3 + 0] - cx;
        const float ry = xb[nb * 3 + 1] - cy;
        const float rz = xb[nb * 3 + 2] - cz;

        // --- layer1 fused into layer2 accumulation ---
        float h2[64];
#pragma unroll
        for (int o = 0; o < 64; o++) h2[o] = b2s[o];

        for (int c = 0; c < 64; c++) {
            float a = fmaf(rx, w1s[c * 3 + 0], b1s[c]);
            a = fmaf(ry, w1s[c * 3 + 1], a);
            a = fmaf(rz, w1s[c * 3 + 2], a);
            float hv = fmaxf(a, 0.0f);
            const float4* row = (const float4*)(w2t + c * 64);
#pragma unroll
            for (int o4 = 0; o4 < 16; o4++) {
                float4 wv = row[o4];
                h2[o4 * 4 + 0] = fmaf(hv, wv.x, h2[o4 * 4 + 0]);
                h2[o4 * 4 + 1] = fmaf(hv, wv.y, h2[o4 * 4 + 1]);
                h2[o4 * 4 + 2] = fmaf(hv, wv.z, h2[o4 * 4 + 2]);
                h2[o4 * 4 + 3] = fmaf(hv, wv.w, h2[o4 * 4 + 3]);
            }
        }
#pragma unroll
        for (int o = 0; o < 64; o++) h2[o] = fmaxf(h2[o], 0.0f);

        // --- layer3 + relu + warp max-pool ---
        float* outb = out + (size_t)BATCH * 3 * NS + (size_t)b * 128 * NS + s;
        for (int o = 0; o < 128; o++) {
            float a = b3s[o];
            const float4* row = (const float4*)(w3s + o * 64);
#pragma unroll
            for (int c4 = 0; c4 < 16; c4++) {
                float4 wv = row[c4];
                a = fmaf(h2[c4 * 4 + 0], wv.x, a);
                a = fmaf(h2[c4 * 4 + 1], wv.y, a);
                a = fmaf(h2[c4 * 4 + 2], wv.z, a);
                a = fmaf(h2[c4 * 4 + 3], wv.w, a);
            }
            a = fmaxf(a, 0.0f);
#pragma unroll
            for (int off = 16; off; off >>= 1)
                a = fmaxf(a, __shfl_xor_sync(0xffffffffu, a, off));
            if (lane == 0) outb[(size_t)o * NS] = a;
        }
    }
}

// ---------------------------------------------------------------------------
extern "C" void kernel_launch(void* const* d_in, const int* in_sizes, int n_in,
                              void* d_out, int out_size)
{
    const float* xyz = (const float*)d_in[0];
    const float* w1 = (const float*)d_in[2];
    const float* b1 = (const float*)d_in[3];
    const float* w2 = (const float*)d_in[4];
    const float* b2 = (const float*)d_in[5];
    const float* w3 = (const float*)d_in[6];
    const float* b3 = (const float*)d_in[7];

    float* out = (float*)d_out;

    const int smem = 3 * NPTS * sizeof(float);   // 96 KB
    cudaFuncSetAttribute(fused_kernel,
                         cudaFuncAttributeMaxDynamicSharedMemorySize, smem);

    const int nmlp = (BATCH * NS) / NWARP;       // 1024 consumer blocks
    reset_kernel<<<1, 32>>>();
    fused_kernel<<<BATCH + nmlp, TB, smem>>>(xyz, w1, b1, w2, b2, w3, b3, out);
}